// round 12
// baseline (speedup 1.0000x reference)
#include <cuda_runtime.h>
#include <cuda_bf16.h>
#include <cstdint>

#define BB 32
#define TT 2048
#define VV 128
#define LL 256
#define SS 513            // 2*L+1
#define NTHR 256          // 8 warps; thread i owns states 2i, 2i+1 (+512 on i=255)
#define NWARP 8
#define RING 64
#define EDEAD (-(1 << 20))   // dead sentinel; with drift stays within 24-bit pack
#define LN2F 0.6931471805599453f

// Scratch: penalty-adjusted softmax probabilities [B][T][V]  (~33.5 MB)
__device__ __align__(16) float g_p[(size_t)BB * TT * VV];
__device__ float g_loss[BB];

__device__ __forceinline__ float penalty_of(int v) {
    if (v == 0 || v == 3) return 1.0f;
    if (v == 11 || v == 15 || v == 19 || v == 25 || v == 31) return 5.0f;
    return 0.0f;
}

// 2^d, exact; flushes to 0 for d <= -127. Callers guarantee d <= 127.
__device__ __forceinline__ float p2n(int d) {
    int be = 127 + d;
    be = be < 0 ? 0 : be;
    return __int_as_float((uint32_t)be << 23);
}

// halo word: [mantissa bits : 32][exponent : 24][tag : 8]
__device__ __forceinline__ unsigned long long hpack(float m, int e, int tag) {
    return ((unsigned long long)__float_as_uint(m) << 32)
         | (unsigned)(((unsigned)e << 8) | (unsigned)tag);
}

// ---------------------------------------------------------------------------
// Pass 1: p[b,t,v] = softmax_v(y_pred - penalty)   (linear domain)
// ---------------------------------------------------------------------------
__global__ void prob_kernel(const float* __restrict__ y_pred) {
    int gwarp = (blockIdx.x * blockDim.x + threadIdx.x) >> 5;
    int lane  = threadIdx.x & 31;
    if (gwarp >= BB * TT) return;

    const float4* row = reinterpret_cast<const float4*>(y_pred + (size_t)gwarp * VV);
    float4 x = row[lane];
    int v0 = lane * 4;
    x.x -= penalty_of(v0 + 0);
    x.y -= penalty_of(v0 + 1);
    x.z -= penalty_of(v0 + 2);
    x.w -= penalty_of(v0 + 3);

    float m = fmaxf(fmaxf(x.x, x.y), fmaxf(x.z, x.w));
    #pragma unroll
    for (int o = 16; o > 0; o >>= 1)
        m = fmaxf(m, __shfl_xor_sync(0xffffffffu, m, o));

    float s = __expf(x.x - m) + __expf(x.y - m) + __expf(x.z - m) + __expf(x.w - m);
    #pragma unroll
    for (int o = 16; o > 0; o >>= 1)
        s += __shfl_xor_sync(0xffffffffu, s, o);

    float lse = m + __logf(s);
    float4 out;
    out.x = __expf(x.x - lse);
    out.y = __expf(x.y - lse);
    out.z = __expf(x.z - lse);
    out.w = __expf(x.w - lse);
    reinterpret_cast<float4*>(g_p + (size_t)gwarp * VV)[lane] = out;
}

// ---------------------------------------------------------------------------
// Pass 2: CTC forward, barrier-free skewed-warp pipeline.
// Thread i holds (mE, mO[, mX]) sharing one exponent e. Cross-warp halo goes
// through a 64-deep ring of packed volatile 64-bit words (tag-in-word).
// Back-pressure: per-warp progress word, checked every 32 steps.
// ---------------------------------------------------------------------------
__global__ void __launch_bounds__(NTHR, 1) ctc_kernel(const int* __restrict__ y_true) {
    __shared__ int   sh_lab[LL];
    __shared__ int   sh_len;
    __shared__ float sM[2 * NTHR + 1];
    __shared__ int   sG[2 * NTHR + 1];
    __shared__ volatile unsigned long long ring[NWARP - 1][RING];
    __shared__ volatile int prog[NWARP];

    const int b    = blockIdx.x;
    const int tid  = threadIdx.x;
    const int lane = tid & 31;
    const int w    = tid >> 5;
    const bool last = (tid == NTHR - 1);

    sh_lab[tid] = y_true[b * LL + tid];
    if (tid == 0) sh_len = 0;
    if (tid < NWARP) prog[tid] = 0;
    // poison ring tags: slot s gets tag (s+1), which never matches a real tag
    // for that slot (real tags are s + 64k mod 256).
    for (int i = tid; i < (NWARP - 1) * RING; i += NTHR)
        ring[i >> 6][i & (RING - 1)] = (unsigned long long)(((i & (RING - 1)) + 1) & 0xff);
    __syncthreads();
    if (sh_lab[tid] != 0) atomicAdd(&sh_len, 1);

    const int ext = sh_lab[tid];               // label of odd state 2*tid+1
    const bool skip = (tid > 0) && (ext != 0) && (ext != sh_lab[tid - 1]);

    const float* pb = g_p + (size_t)b * TT * VV;

    // ----- t=0 init: only states 0, 1 live (thread 0) -----
    float mE = 0.f, mO = 0.f, mX = 0.f;
    int   e  = EDEAD;
    if (tid == 0) {
        float vE = pb[0], vO = pb[ext];
        int eE = (__float_as_int(vE) >> 23) - 127;
        int eO = (__float_as_int(vO) >> 23) - 127;
        e  = max(eE, eO);
        mE = vE * p2n(-e);
        mO = vO * p2n(-e);
    }
    __syncthreads();   // sh_len finalized; ring poison visible before first publish
    if (lane == 31 && w < NWARP - 1)
        ring[w][0] = hpack(mO, e, 0);          // step-0 halo

    // prob queues for t = 1..4 (slot u consumed at t = 4*blk+1+u)
    float qb[4], q1[4];
    #pragma unroll
    for (int u = 0; u < 4; ++u) {
        const float* row = pb + (size_t)(1 + u) * VV;
        qb[u] = row[0];
        q1[u] = row[ext];
    }
    const float* rp = pb + (size_t)5 * VV;     // refill source (row t+4 at t=1)

    for (int blk = 0; blk < 512; ++blk) {
        #pragma unroll
        for (int u = 0; u < 4; ++u) {
            const int t = 4 * blk + 1 + u;
            if (t < TT) {
                // ---- consume halo (state 32w-1 at step t-1) ----
                float hm = 0.f; int he = EDEAD;
                if (w > 0) {
                    const unsigned exp_tag = (unsigned)((t - 1) & 0xff);
                    volatile unsigned long long* slot = &ring[w - 1][(t - 1) & (RING - 1)];
                    unsigned long long v;
                    do { v = *slot; } while ((unsigned)(v & 0xffu) != exp_tag);
                    he = ((int)(unsigned)(v & 0xffffffffu)) >> 8;   // sign-extends
                    hm = __uint_as_float((unsigned)(v >> 32));
                }
                float pm = __shfl_up_sync(0xffffffffu, mO, 1);
                int   pe = __shfl_up_sync(0xffffffffu, e, 1);
                if (lane == 0) { pm = hm; pe = he; }

                // ---- update (identical numerics to the passing R7 kernel) ----
                int   em  = max(e, pe);
                float fs  = p2n(e  - em);
                float fp  = p2n(pe - em);
                float fpg = skip ? fp : 0.f;

                float aE = fmaf(mE, fs, pm * fp)  * qb[u];          // blank 2i
                float aO = fmaf(mE + mO, fs, pm * fpg) * q1[u];     // label 2i+1
                float aX = 0.f;
                if (last) aX = (mX + mO) * fs * qb[u];              // blank 512

                float big = fmaxf(aE, aO);
                if (last) big = fmaxf(big, aX);
                int ad = (__float_as_int(big) >> 23) - 127;
                e = em + ad;
                float sc = p2n(-ad);
                mE = aE * sc;
                mO = aO * sc;
                if (last) mX = aX * sc;

                // ---- publish halo for step t ----
                if (lane == 31 && w < NWARP - 1)
                    ring[w][t & (RING - 1)] = hpack(mO, e, t & 0xff);

                // ---- progress + back-pressure every 32 steps ----
                if ((t & 31) == 0) {
                    if (w > 0 && lane == 0) prog[w] = t;
                    if (w < NWARP - 1) {
                        while (prog[w + 1] < t - 32) { }
                    }
                }
            }
            if (t + 4 < TT) {
                qb[u] = rp[0];
                q1[u] = rp[ext];
            }
            rp += VV;
        }
    }

    __syncthreads();   // all warps (skewed) finished
    // ----- readout -----
    sM[2 * tid]     = mE; sG[2 * tid]     = e;
    sM[2 * tid + 1] = mO; sG[2 * tid + 1] = e;
    if (last) { sM[2 * NTHR] = mX; sG[2 * NTHR] = e; }
    __syncthreads();
    if (tid == 0) {
        int il = 2 * sh_len, ip = il - 1;      // il in [256, 512]
        float ma = sM[il]; int ga = sG[il];
        float mb = sM[ip]; int gb = sG[ip];
        float la = (ma > 0.f) ? (float)ga + __log2f(ma) : -3.0e8f;
        float lb = (mb > 0.f) ? (float)gb + __log2f(mb) : -3.0e8f;
        float mx = fmaxf(la, lb);
        float ll2 = mx + __log2f(exp2f(la - mx) + exp2f(lb - mx));
        g_loss[b] = -ll2 * LN2F;
    }
}

// ---------------------------------------------------------------------------
// Pass 3: mean over batch + 1e-7
// ---------------------------------------------------------------------------
__global__ void finalize_kernel(float* __restrict__ out) {
    int t = threadIdx.x;
    float v = g_loss[t];
    #pragma unroll
    for (int o = 16; o > 0; o >>= 1)
        v += __shfl_xor_sync(0xffffffffu, v, o);
    if (t == 0) out[0] = v * (1.0f / (float)BB) + 1e-7f;
}

extern "C" void kernel_launch(void* const* d_in, const int* in_sizes, int n_in,
                              void* d_out, int out_size) {
    const float* y_pred = (const float*)d_in[0];
    const int*   y_true = (const int*)d_in[1];
    float*       out    = (float*)d_out;

    prob_kernel<<<(BB * TT) / 8, 256>>>(y_pred);
    ctc_kernel<<<BB, NTHR>>>(y_true);
    finalize_kernel<<<1, 32>>>(out);
}

// round 13
// speedup vs baseline: 1.2326x; 1.2326x over previous
#include <cuda_runtime.h>
#include <cuda_bf16.h>
#include <cstdint>

#define BB 32
#define TT 2048
#define VV 128
#define LL 256
#define SS 513            // 2*L+1
#define NTHR 256          // 8 warps; thread i owns states 2i, 2i+1 (+512 on i=255)
#define NWARP 8
#define EDEAD (-(1 << 28))
#define LN2F 0.6931471805599453f

// Scratch: penalty-adjusted softmax probabilities [B][T][V]  (~33.5 MB)
__device__ __align__(16) float g_p[(size_t)BB * TT * VV];
__device__ float g_loss[BB];

__device__ __forceinline__ float penalty_of(int v) {
    if (v == 0 || v == 3) return 1.0f;
    if (v == 11 || v == 15 || v == 19 || v == 25 || v == 31) return 5.0f;
    return 0.0f;
}

// 2^d, exact; flushes to 0 for d <= -127. Callers guarantee d <= 127.
__device__ __forceinline__ float p2n(int d) {
    int be = 127 + d;
    be = be < 0 ? 0 : be;
    return __int_as_float((uint32_t)be << 23);
}

// ---------------------------------------------------------------------------
// Pass 1: p[b,t,v] = softmax_v(y_pred - penalty)   (linear domain)
// ---------------------------------------------------------------------------
__global__ void prob_kernel(const float* __restrict__ y_pred) {
    int gwarp = (blockIdx.x * blockDim.x + threadIdx.x) >> 5;
    int lane  = threadIdx.x & 31;
    if (gwarp >= BB * TT) return;

    const float4* row = reinterpret_cast<const float4*>(y_pred + (size_t)gwarp * VV);
    float4 x = row[lane];
    int v0 = lane * 4;
    x.x -= penalty_of(v0 + 0);
    x.y -= penalty_of(v0 + 1);
    x.z -= penalty_of(v0 + 2);
    x.w -= penalty_of(v0 + 3);

    float m = fmaxf(fmaxf(x.x, x.y), fmaxf(x.z, x.w));
    #pragma unroll
    for (int o = 16; o > 0; o >>= 1)
        m = fmaxf(m, __shfl_xor_sync(0xffffffffu, m, o));

    float s = __expf(x.x - m) + __expf(x.y - m) + __expf(x.z - m) + __expf(x.w - m);
    #pragma unroll
    for (int o = 16; o > 0; o >>= 1)
        s += __shfl_xor_sync(0xffffffffu, s, o);

    float lse = m + __logf(s);
    float4 out;
    out.x = __expf(x.x - lse);
    out.y = __expf(x.y - lse);
    out.z = __expf(x.z - lse);
    out.w = __expf(x.w - lse);
    reinterpret_cast<float4*>(g_p + (size_t)gwarp * VV)[lane] = out;
}

// ---------------------------------------------------------------------------
// Pass 2: CTC forward, 2 time-steps fused per __syncthreads.
// Thread i holds (mE, mO[, mX]) sharing one exponent frame e.
// Per pair: shfl-up(1) of (mE,mO,e) and shfl-up(2) of (mO,e); thread i
// redundantly recomputes state 2i-1 at the intermediate step.
// ---------------------------------------------------------------------------
__global__ void __launch_bounds__(NTHR, 1) ctc_kernel(const int* __restrict__ y_true) {
    __shared__ int   sh_lab[LL];
    __shared__ int   sh_len;
    __shared__ float sM[2 * NTHR + 1];
    __shared__ int   sG[2 * NTHR + 1];
    // halo (producer warp w -> consumer warp w+1), double-buffered by pair parity
    __shared__ float hE31[2][NWARP], hO31[2][NWARP], hO30[2][NWARP];
    __shared__ int   he31[2][NWARP], he30[2][NWARP];

    const int b    = blockIdx.x;
    const int tid  = threadIdx.x;
    const int lane = tid & 31;
    const int w    = tid >> 5;
    const bool last = (tid == NTHR - 1);

    sh_lab[tid] = y_true[b * LL + tid];
    if (tid == 0) sh_len = 0;
    __syncthreads();
    if (sh_lab[tid] != 0) atomicAdd(&sh_len, 1);

    const int  ext  = sh_lab[tid];                       // label of odd state 2i+1
    const bool skip = (tid > 0) && (ext != 0) && (ext != sh_lab[tid - 1]);
    const int  extP = (tid > 0) ? sh_lab[tid - 1] : 0;   // label of state 2i-1
    const bool skipP = (tid > 1) && (extP != 0) && (extP != sh_lab[tid - 2]);

    const float* pb = g_p + (size_t)b * TT * VV;

    // ----- preload: standalone step t=1 probs + pair buffers (pairs 1,2,3) -----
    float sqb = pb[VV], sq1 = pb[VV + ext];
    float qb0[3], qb1[3], q11[3], q12[3], q1p[3];
    #pragma unroll
    for (int j = 0; j < 3; ++j) {
        const float* rA = pb + (size_t)(2 * (j + 1)) * VV;
        const float* rB = rA + VV;
        qb0[j] = rA[0];   qb1[j] = rB[0];
        q11[j] = rA[ext]; q12[j] = rB[ext];
        q1p[j] = rA[extP];
    }

    // ----- t=0 init: only states 0, 1 live (thread 0) -----
    float mE = 0.f, mO = 0.f, mX = 0.f;
    int   e  = EDEAD;
    if (tid == 0) {
        float vE = pb[0], vO = pb[ext];
        int eE = (__float_as_int(vE) >> 23) - 127;
        int eO = (__float_as_int(vO) >> 23) - 127;
        e  = max(eE, eO);
        mE = vE * p2n(-e);
        mO = vO * p2n(-e);
    }
    if (lane == 31 && w < NWARP - 1) { hO31[1][w] = mO; he31[1][w] = e; }
    __syncthreads();

    // ----- standalone step t=1 (R7 single-step) -----
    {
        float pm = __shfl_up_sync(0xffffffffu, mO, 1);
        int   pe = __shfl_up_sync(0xffffffffu, e, 1);
        if (lane == 0) {
            if (w > 0) { pm = hO31[1][w - 1]; pe = he31[1][w - 1]; }
            else       { pm = 0.f; pe = EDEAD; }
        }
        int   em  = max(e, pe);
        float fs  = p2n(e - em), fp = p2n(pe - em);
        float fpg = skip ? fp : 0.f;
        float aE = fmaf(mE, fs, pm * fp) * sqb;
        float aO = fmaf(mE + mO, fs, pm * fpg) * sq1;
        float aX = last ? (mX + mO) * fs * sqb : 0.f;
        float big = fmaxf(aE, aO);
        if (last) big = fmaxf(big, aX);
        int ad = (__float_as_int(big) >> 23) - 127;
        e = em + ad;
        float sc = p2n(-ad);
        mE = aE * sc; mO = aO * sc;
        if (last) mX = aX * sc;
    }
    if (w < NWARP - 1) {
        if (lane == 31) { hE31[0][w] = mE; hO31[0][w] = mO; he31[0][w] = e; }
        if (lane == 30) { hO30[0][w] = mO; he30[0][w] = e; }
    }
    __syncthreads();

    // ----- pair loop: pair k covers steps t = 2k, 2k+1 ; k = 1..1023 -----
    #pragma unroll 3
    for (int k = 1; k <= 1023; ++k) {
        const int j    = (k - 1) % 3;
        const int parR = (k - 1) & 1;
        const int parW = k & 1;

        float nE  = __shfl_up_sync(0xffffffffu, mE, 1);
        float nO  = __shfl_up_sync(0xffffffffu, mO, 1);
        int   ne  = __shfl_up_sync(0xffffffffu, e, 1);
        float n2O = __shfl_up_sync(0xffffffffu, mO, 2);
        int   n2e = __shfl_up_sync(0xffffffffu, e, 2);
        if (lane == 0) {
            if (w > 0) {
                nE = hE31[parR][w - 1]; nO = hO31[parR][w - 1]; ne = he31[parR][w - 1];
                n2O = hO30[parR][w - 1]; n2e = he30[parR][w - 1];
            } else { nE = 0.f; nO = 0.f; ne = EDEAD; n2O = 0.f; n2e = EDEAD; }
        }
        if (lane == 1) {
            if (w > 0) { n2O = hO31[parR][w - 1]; n2e = he31[parR][w - 1]; }
            else       { n2O = 0.f; n2e = EDEAD; }
        }

        // ---- step A (t = 2k): own states in frame emA ----
        int   emA = max(e, ne);
        float fsA = p2n(e - emA), fpA = p2n(ne - emA);
        float aE = fmaf(mE, fsA, nO * fpA) * qb0[j];
        float aO = fmaf(mE + mO, fsA, nO * (skip ? fpA : 0.f)) * q11[j];
        float aX = last ? (mX + mO) * fsA * qb0[j] : 0.f;
        // recomputed neighbor state 2i-1 in frame emP
        int   emP = max(ne, n2e);
        float fsP = p2n(ne - emP), fpP = p2n(n2e - emP);
        float aP  = fmaf(nE + nO, fsP, n2O * (skipP ? fpP : 0.f)) * q1p[j];

        // ---- step B (t = 2k+1): frame emB ----
        int   emB = max(emA, emP);
        float fsB = p2n(emA - emB), fpB = p2n(emP - emB);
        float bE = fmaf(aE, fsB, aP * fpB) * qb1[j];
        float bO = fmaf(aE + aO, fsB, aP * (skip ? fpB : 0.f)) * q12[j];
        float bX = last ? (aX + aO) * fsB * qb1[j] : 0.f;

        // ---- renorm ----
        float big = fmaxf(bE, bO);
        if (last) big = fmaxf(big, bX);
        int ad = (__float_as_int(big) >> 23) - 127;
        e = emB + ad;
        float sc = p2n(-ad);
        mE = bE * sc; mO = bO * sc;
        if (last) mX = bX * sc;

        if (w < NWARP - 1) {
            if (lane == 31) { hE31[parW][w] = mE; hO31[parW][w] = mO; he31[parW][w] = e; }
            if (lane == 30) { hO30[parW][w] = mO; he30[parW][w] = e; }
        }

        // refill buffer j with pair k+3 (rows 2k+6, 2k+7)
        if (k + 3 <= 1023) {
            const float* rA = pb + (size_t)(2 * k + 6) * VV;
            const float* rB = rA + VV;
            qb0[j] = rA[0];   qb1[j] = rB[0];
            q11[j] = rA[ext]; q12[j] = rB[ext];
            q1p[j] = rA[extP];
        }
        __syncthreads();
    }

    // ----- readout -----
    sM[2 * tid]     = mE; sG[2 * tid]     = e;
    sM[2 * tid + 1] = mO; sG[2 * tid + 1] = e;
    if (last) { sM[2 * NTHR] = mX; sG[2 * NTHR] = e; }
    __syncthreads();
    if (tid == 0) {
        int il = 2 * sh_len, ip = il - 1;      // il in [256, 512]
        float ma = sM[il]; int ga = sG[il];
        float mb = sM[ip]; int gb = sG[ip];
        float la = (ma > 0.f) ? (float)ga + __log2f(ma) : -3.0e8f;
        float lb = (mb > 0.f) ? (float)gb + __log2f(mb) : -3.0e8f;
        float mx = fmaxf(la, lb);
        float ll2 = mx + __log2f(exp2f(la - mx) + exp2f(lb - mx));
        g_loss[b] = -ll2 * LN2F;
    }
}

// ---------------------------------------------------------------------------
// Pass 3: mean over batch + 1e-7
// ---------------------------------------------------------------------------
__global__ void finalize_kernel(float* __restrict__ out) {
    int t = threadIdx.x;
    float v = g_loss[t];
    #pragma unroll
    for (int o = 16; o > 0; o >>= 1)
        v += __shfl_xor_sync(0xffffffffu, v, o);
    if (t == 0) out[0] = v * (1.0f / (float)BB) + 1e-7f;
}

extern "C" void kernel_launch(void* const* d_in, const int* in_sizes, int n_in,
                              void* d_out, int out_size) {
    const float* y_pred = (const float*)d_in[0];
    const int*   y_true = (const int*)d_in[1];
    float*       out    = (float*)d_out;

    prob_kernel<<<(BB * TT) / 8, 256>>>(y_pred);
    ctc_kernel<<<BB, NTHR>>>(y_true);
    finalize_kernel<<<1, 32>>>(out);
}

// round 14
// speedup vs baseline: 1.2335x; 1.0007x over previous
#include <cuda_runtime.h>
#include <cuda_bf16.h>
#include <cstdint>

#define BB 32
#define TT 2048
#define VV 128
#define LL 256
#define SS 513            // 2*L+1
#define NTHR 256          // 8 warps; thread i owns states 2i, 2i+1 (+512 on i=255)
#define NWARP 8
#define EDEAD (-(1 << 28))
#define LN2F 0.6931471805599453f

// Scratch: penalty-adjusted softmax probabilities [B][T][V]  (~33.5 MB)
__device__ __align__(16) float g_p[(size_t)BB * TT * VV];
__device__ float g_loss[BB];

__device__ __forceinline__ float penalty_of(int v) {
    if (v == 0 || v == 3) return 1.0f;
    if (v == 11 || v == 15 || v == 19 || v == 25 || v == 31) return 5.0f;
    return 0.0f;
}

// 2^d, exact; flushes to 0 for d <= -127. Callers guarantee d <= 127.
__device__ __forceinline__ float p2n(int d) {
    int be = 127 + d;
    be = be < 0 ? 0 : be;
    return __int_as_float((uint32_t)be << 23);
}

// ---------------------------------------------------------------------------
// Pass 1: p[b,t,v] = softmax_v(y_pred - penalty)   (linear domain)
// ---------------------------------------------------------------------------
__global__ void prob_kernel(const float* __restrict__ y_pred) {
    int gwarp = (blockIdx.x * blockDim.x + threadIdx.x) >> 5;
    int lane  = threadIdx.x & 31;
    if (gwarp >= BB * TT) return;

    const float4* row = reinterpret_cast<const float4*>(y_pred + (size_t)gwarp * VV);
    float4 x = row[lane];
    int v0 = lane * 4;
    x.x -= penalty_of(v0 + 0);
    x.y -= penalty_of(v0 + 1);
    x.z -= penalty_of(v0 + 2);
    x.w -= penalty_of(v0 + 3);

    float m = fmaxf(fmaxf(x.x, x.y), fmaxf(x.z, x.w));
    #pragma unroll
    for (int o = 16; o > 0; o >>= 1)
        m = fmaxf(m, __shfl_xor_sync(0xffffffffu, m, o));

    float s = __expf(x.x - m) + __expf(x.y - m) + __expf(x.z - m) + __expf(x.w - m);
    #pragma unroll
    for (int o = 16; o > 0; o >>= 1)
        s += __shfl_xor_sync(0xffffffffu, s, o);

    float lse = m + __logf(s);
    float4 out;
    out.x = __expf(x.x - lse);
    out.y = __expf(x.y - lse);
    out.z = __expf(x.z - lse);
    out.w = __expf(x.w - lse);
    reinterpret_cast<float4*>(g_p + (size_t)gwarp * VV)[lane] = out;
}

// ---------------------------------------------------------------------------
// Pass 2: CTC forward, 2 time-steps fused per __syncthreads.
// Thread i holds (mE, mO[, mX]) sharing one exponent frame e.
// Per pair: shfl-up(1) of (mE,mO,e) and shfl-up(2) of (mO,e); thread i
// redundantly recomputes state 2i-1 at the intermediate step.
// ---------------------------------------------------------------------------
__global__ void __launch_bounds__(NTHR, 1) ctc_kernel(const int* __restrict__ y_true) {
    __shared__ int   sh_lab[LL];
    __shared__ int   sh_len;
    __shared__ float sM[2 * NTHR + 1];
    __shared__ int   sG[2 * NTHR + 1];
    // halo (producer warp w -> consumer warp w+1), double-buffered by pair parity
    __shared__ float hE31[2][NWARP], hO31[2][NWARP], hO30[2][NWARP];
    __shared__ int   he31[2][NWARP], he30[2][NWARP];

    const int b    = blockIdx.x;
    const int tid  = threadIdx.x;
    const int lane = tid & 31;
    const int w    = tid >> 5;
    const bool last = (tid == NTHR - 1);

    sh_lab[tid] = y_true[b * LL + tid];
    if (tid == 0) sh_len = 0;
    __syncthreads();
    if (sh_lab[tid] != 0) atomicAdd(&sh_len, 1);

    const int  ext  = sh_lab[tid];                       // label of odd state 2i+1
    const bool skip = (tid > 0) && (ext != 0) && (ext != sh_lab[tid - 1]);
    const int  extP = (tid > 0) ? sh_lab[tid - 1] : 0;   // label of state 2i-1
    const bool skipP = (tid > 1) && (extP != 0) && (extP != sh_lab[tid - 2]);

    const float* pb = g_p + (size_t)b * TT * VV;

    // ----- preload: standalone step t=1 probs + pair buffers (pairs 1,2,3) -----
    float sqb = pb[VV], sq1 = pb[VV + ext];
    float qb0[3], qb1[3], q11[3], q12[3], q1p[3];
    #pragma unroll
    for (int j = 0; j < 3; ++j) {
        const float* rA = pb + (size_t)(2 * (j + 1)) * VV;
        const float* rB = rA + VV;
        qb0[j] = rA[0];   qb1[j] = rB[0];
        q11[j] = rA[ext]; q12[j] = rB[ext];
        q1p[j] = rA[extP];
    }

    // ----- t=0 init: only states 0, 1 live (thread 0) -----
    float mE = 0.f, mO = 0.f, mX = 0.f;
    int   e  = EDEAD;
    if (tid == 0) {
        float vE = pb[0], vO = pb[ext];
        int eE = (__float_as_int(vE) >> 23) - 127;
        int eO = (__float_as_int(vO) >> 23) - 127;
        e  = max(eE, eO);
        mE = vE * p2n(-e);
        mO = vO * p2n(-e);
    }
    if (lane == 31 && w < NWARP - 1) { hO31[1][w] = mO; he31[1][w] = e; }
    __syncthreads();

    // ----- standalone step t=1 (R7 single-step) -----
    {
        float pm = __shfl_up_sync(0xffffffffu, mO, 1);
        int   pe = __shfl_up_sync(0xffffffffu, e, 1);
        if (lane == 0) {
            if (w > 0) { pm = hO31[1][w - 1]; pe = he31[1][w - 1]; }
            else       { pm = 0.f; pe = EDEAD; }
        }
        int   em  = max(e, pe);
        float fs  = p2n(e - em), fp = p2n(pe - em);
        float fpg = skip ? fp : 0.f;
        float aE = fmaf(mE, fs, pm * fp) * sqb;
        float aO = fmaf(mE + mO, fs, pm * fpg) * sq1;
        float aX = last ? (mX + mO) * fs * sqb : 0.f;
        float big = fmaxf(aE, aO);
        if (last) big = fmaxf(big, aX);
        int ad = (__float_as_int(big) >> 23) - 127;
        e = em + ad;
        float sc = p2n(-ad);
        mE = aE * sc; mO = aO * sc;
        if (last) mX = aX * sc;
    }
    if (w < NWARP - 1) {
        if (lane == 31) { hE31[0][w] = mE; hO31[0][w] = mO; he31[0][w] = e; }
        if (lane == 30) { hO30[0][w] = mO; he30[0][w] = e; }
    }
    __syncthreads();

    // ----- pair loop: pair k covers steps t = 2k, 2k+1 ; k = 1..1023 -----
    #pragma unroll 3
    for (int k = 1; k <= 1023; ++k) {
        const int j    = (k - 1) % 3;
        const int parR = (k - 1) & 1;
        const int parW = k & 1;

        float nE  = __shfl_up_sync(0xffffffffu, mE, 1);
        float nO  = __shfl_up_sync(0xffffffffu, mO, 1);
        int   ne  = __shfl_up_sync(0xffffffffu, e, 1);
        float n2O = __shfl_up_sync(0xffffffffu, mO, 2);
        int   n2e = __shfl_up_sync(0xffffffffu, e, 2);
        if (lane == 0) {
            if (w > 0) {
                nE = hE31[parR][w - 1]; nO = hO31[parR][w - 1]; ne = he31[parR][w - 1];
                n2O = hO30[parR][w - 1]; n2e = he30[parR][w - 1];
            } else { nE = 0.f; nO = 0.f; ne = EDEAD; n2O = 0.f; n2e = EDEAD; }
        }
        if (lane == 1) {
            if (w > 0) { n2O = hO31[parR][w - 1]; n2e = he31[parR][w - 1]; }
            else       { n2O = 0.f; n2e = EDEAD; }
        }

        // ---- step A (t = 2k): own states in frame emA ----
        int   emA = max(e, ne);
        float fsA = p2n(e - emA), fpA = p2n(ne - emA);
        float aE = fmaf(mE, fsA, nO * fpA) * qb0[j];
        float aO = fmaf(mE + mO, fsA, nO * (skip ? fpA : 0.f)) * q11[j];
        float aX = last ? (mX + mO) * fsA * qb0[j] : 0.f;
        // recomputed neighbor state 2i-1 in frame emP
        int   emP = max(ne, n2e);
        float fsP = p2n(ne - emP), fpP = p2n(n2e - emP);
        float aP  = fmaf(nE + nO, fsP, n2O * (skipP ? fpP : 0.f)) * q1p[j];

        // ---- step B (t = 2k+1): frame emB ----
        int   emB = max(emA, emP);
        float fsB = p2n(emA - emB), fpB = p2n(emP - emB);
        float bE = fmaf(aE, fsB, aP * fpB) * qb1[j];
        float bO = fmaf(aE + aO, fsB, aP * (skip ? fpB : 0.f)) * q12[j];
        float bX = last ? (aX + aO) * fsB * qb1[j] : 0.f;

        // ---- renorm ----
        float big = fmaxf(bE, bO);
        if (last) big = fmaxf(big, bX);
        int ad = (__float_as_int(big) >> 23) - 127;
        e = emB + ad;
        float sc = p2n(-ad);
        mE = bE * sc; mO = bO * sc;
        if (last) mX = bX * sc;

        if (w < NWARP - 1) {
            if (lane == 31) { hE31[parW][w] = mE; hO31[parW][w] = mO; he31[parW][w] = e; }
            if (lane == 30) { hO30[parW][w] = mO; he30[parW][w] = e; }
        }

        // refill buffer j with pair k+3 (rows 2k+6, 2k+7)
        if (k + 3 <= 1023) {
            const float* rA = pb + (size_t)(2 * k + 6) * VV;
            const float* rB = rA + VV;
            qb0[j] = rA[0];   qb1[j] = rB[0];
            q11[j] = rA[ext]; q12[j] = rB[ext];
            q1p[j] = rA[extP];
        }
        __syncthreads();
    }

    // ----- readout -----
    sM[2 * tid]     = mE; sG[2 * tid]     = e;
    sM[2 * tid + 1] = mO; sG[2 * tid + 1] = e;
    if (last) { sM[2 * NTHR] = mX; sG[2 * NTHR] = e; }
    __syncthreads();
    if (tid == 0) {
        int il = 2 * sh_len, ip = il - 1;      // il in [256, 512]
        float ma = sM[il]; int ga = sG[il];
        float mb = sM[ip]; int gb = sG[ip];
        float la = (ma > 0.f) ? (float)ga + __log2f(ma) : -3.0e8f;
        float lb = (mb > 0.f) ? (float)gb + __log2f(mb) : -3.0e8f;
        float mx = fmaxf(la, lb);
        float ll2 = mx + __log2f(exp2f(la - mx) + exp2f(lb - mx));
        g_loss[b] = -ll2 * LN2F;
    }
}

// ---------------------------------------------------------------------------
// Pass 3: mean over batch + 1e-7
// ---------------------------------------------------------------------------
__global__ void finalize_kernel(float* __restrict__ out) {
    int t = threadIdx.x;
    float v = g_loss[t];
    #pragma unroll
    for (int o = 16; o > 0; o >>= 1)
        v += __shfl_xor_sync(0xffffffffu, v, o);
    if (t == 0) out[0] = v * (1.0f / (float)BB) + 1e-7f;
}

extern "C" void kernel_launch(void* const* d_in, const int* in_sizes, int n_in,
                              void* d_out, int out_size) {
    const float* y_pred = (const float*)d_in[0];
    const int*   y_true = (const int*)d_in[1];
    float*       out    = (float*)d_out;

    prob_kernel<<<(BB * TT) / 8, 256>>>(y_pred);
    ctc_kernel<<<BB, NTHR>>>(y_true);
    finalize_kernel<<<1, 32>>>(out);
}

// round 15
// speedup vs baseline: 1.2340x; 1.0004x over previous
#include <cuda_runtime.h>
#include <cuda_bf16.h>
#include <cstdint>

#define BB 32
#define TT 2048
#define VV 128
#define LL 256
#define SS 513            // 2*L+1
#define NTHR 256          // 8 warps; thread i owns states 2i, 2i+1 (+512 on i=255)
#define NWARP 8
#define EDEAD (-(1 << 28))
#define LN2F 0.6931471805599453f

// Scratch: penalty-adjusted softmax probabilities [B][T][V]  (~33.5 MB)
__device__ __align__(16) float g_p[(size_t)BB * TT * VV];
__device__ float g_loss[BB];

__device__ __forceinline__ float penalty_of(int v) {
    if (v == 0 || v == 3) return 1.0f;
    if (v == 11 || v == 15 || v == 19 || v == 25 || v == 31) return 5.0f;
    return 0.0f;
}

// 2^d, exact; flushes to 0 for d <= -127. Callers guarantee d <= 127.
__device__ __forceinline__ float p2n(int d) {
    int be = 127 + d;
    be = be < 0 ? 0 : be;
    return __int_as_float((uint32_t)be << 23);
}

// ---------------------------------------------------------------------------
// Pass 1: p[b,t,v] = softmax_v(y_pred - penalty)   (linear domain)
// ---------------------------------------------------------------------------
__global__ void prob_kernel(const float* __restrict__ y_pred) {
    int gwarp = (blockIdx.x * blockDim.x + threadIdx.x) >> 5;
    int lane  = threadIdx.x & 31;
    if (gwarp >= BB * TT) return;

    const float4* row = reinterpret_cast<const float4*>(y_pred + (size_t)gwarp * VV);
    float4 x = row[lane];
    int v0 = lane * 4;
    x.x -= penalty_of(v0 + 0);
    x.y -= penalty_of(v0 + 1);
    x.z -= penalty_of(v0 + 2);
    x.w -= penalty_of(v0 + 3);

    float m = fmaxf(fmaxf(x.x, x.y), fmaxf(x.z, x.w));
    #pragma unroll
    for (int o = 16; o > 0; o >>= 1)
        m = fmaxf(m, __shfl_xor_sync(0xffffffffu, m, o));

    float s = __expf(x.x - m) + __expf(x.y - m) + __expf(x.z - m) + __expf(x.w - m);
    #pragma unroll
    for (int o = 16; o > 0; o >>= 1)
        s += __shfl_xor_sync(0xffffffffu, s, o);

    float lse = m + __logf(s);
    float4 out;
    out.x = __expf(x.x - lse);
    out.y = __expf(x.y - lse);
    out.z = __expf(x.z - lse);
    out.w = __expf(x.w - lse);
    reinterpret_cast<float4*>(g_p + (size_t)gwarp * VV)[lane] = out;
}

// ---------------------------------------------------------------------------
// Pass 2: CTC forward, 2 time-steps fused per __syncthreads.
// Thread i holds (mE, mO[, mX]) sharing one exponent frame e.
// Per pair: shfl-up(1) of (mE,mO,e) and shfl-up(2) of (mO,e); thread i
// redundantly recomputes state 2i-1 at the intermediate step.
// ---------------------------------------------------------------------------
__global__ void __launch_bounds__(NTHR, 1) ctc_kernel(const int* __restrict__ y_true) {
    __shared__ int   sh_lab[LL];
    __shared__ int   sh_len;
    __shared__ float sM[2 * NTHR + 1];
    __shared__ int   sG[2 * NTHR + 1];
    // halo (producer warp w -> consumer warp w+1), double-buffered by pair parity
    __shared__ float hE31[2][NWARP], hO31[2][NWARP], hO30[2][NWARP];
    __shared__ int   he31[2][NWARP], he30[2][NWARP];

    const int b    = blockIdx.x;
    const int tid  = threadIdx.x;
    const int lane = tid & 31;
    const int w    = tid >> 5;
    const bool last = (tid == NTHR - 1);

    sh_lab[tid] = y_true[b * LL + tid];
    if (tid == 0) sh_len = 0;
    __syncthreads();
    if (sh_lab[tid] != 0) atomicAdd(&sh_len, 1);

    const int  ext  = sh_lab[tid];                       // label of odd state 2i+1
    const bool skip = (tid > 0) && (ext != 0) && (ext != sh_lab[tid - 1]);
    const int  extP = (tid > 0) ? sh_lab[tid - 1] : 0;   // label of state 2i-1
    const bool skipP = (tid > 1) && (extP != 0) && (extP != sh_lab[tid - 2]);

    const float* pb = g_p + (size_t)b * TT * VV;

    // ----- preload: standalone step t=1 probs + pair buffers (pairs 1,2,3) -----
    float sqb = pb[VV], sq1 = pb[VV + ext];
    float qb0[3], qb1[3], q11[3], q12[3], q1p[3];
    #pragma unroll
    for (int j = 0; j < 3; ++j) {
        const float* rA = pb + (size_t)(2 * (j + 1)) * VV;
        const float* rB = rA + VV;
        qb0[j] = rA[0];   qb1[j] = rB[0];
        q11[j] = rA[ext]; q12[j] = rB[ext];
        q1p[j] = rA[extP];
    }

    // ----- t=0 init: only states 0, 1 live (thread 0) -----
    float mE = 0.f, mO = 0.f, mX = 0.f;
    int   e  = EDEAD;
    if (tid == 0) {
        float vE = pb[0], vO = pb[ext];
        int eE = (__float_as_int(vE) >> 23) - 127;
        int eO = (__float_as_int(vO) >> 23) - 127;
        e  = max(eE, eO);
        mE = vE * p2n(-e);
        mO = vO * p2n(-e);
    }
    if (lane == 31 && w < NWARP - 1) { hO31[1][w] = mO; he31[1][w] = e; }
    __syncthreads();

    // ----- standalone step t=1 (R7 single-step) -----
    {
        float pm = __shfl_up_sync(0xffffffffu, mO, 1);
        int   pe = __shfl_up_sync(0xffffffffu, e, 1);
        if (lane == 0) {
            if (w > 0) { pm = hO31[1][w - 1]; pe = he31[1][w - 1]; }
            else       { pm = 0.f; pe = EDEAD; }
        }
        int   em  = max(e, pe);
        float fs  = p2n(e - em), fp = p2n(pe - em);
        float fpg = skip ? fp : 0.f;
        float aE = fmaf(mE, fs, pm * fp) * sqb;
        float aO = fmaf(mE + mO, fs, pm * fpg) * sq1;
        float aX = last ? (mX + mO) * fs * sqb : 0.f;
        float big = fmaxf(aE, aO);
        if (last) big = fmaxf(big, aX);
        int ad = (__float_as_int(big) >> 23) - 127;
        e = em + ad;
        float sc = p2n(-ad);
        mE = aE * sc; mO = aO * sc;
        if (last) mX = aX * sc;
    }
    if (w < NWARP - 1) {
        if (lane == 31) { hE31[0][w] = mE; hO31[0][w] = mO; he31[0][w] = e; }
        if (lane == 30) { hO30[0][w] = mO; he30[0][w] = e; }
    }
    __syncthreads();

    // ----- pair loop: pair k covers steps t = 2k, 2k+1 ; k = 1..1023 -----
    #pragma unroll 3
    for (int k = 1; k <= 1023; ++k) {
        const int j    = (k - 1) % 3;
        const int parR = (k - 1) & 1;
        const int parW = k & 1;

        float nE  = __shfl_up_sync(0xffffffffu, mE, 1);
        float nO  = __shfl_up_sync(0xffffffffu, mO, 1);
        int   ne  = __shfl_up_sync(0xffffffffu, e, 1);
        float n2O = __shfl_up_sync(0xffffffffu, mO, 2);
        int   n2e = __shfl_up_sync(0xffffffffu, e, 2);
        if (lane == 0) {
            if (w > 0) {
                nE = hE31[parR][w - 1]; nO = hO31[parR][w - 1]; ne = he31[parR][w - 1];
                n2O = hO30[parR][w - 1]; n2e = he30[parR][w - 1];
            } else { nE = 0.f; nO = 0.f; ne = EDEAD; n2O = 0.f; n2e = EDEAD; }
        }
        if (lane == 1) {
            if (w > 0) { n2O = hO31[parR][w - 1]; n2e = he31[parR][w - 1]; }
            else       { n2O = 0.f; n2e = EDEAD; }
        }

        // ---- step A (t = 2k): own states in frame emA ----
        int   emA = max(e, ne);
        float fsA = p2n(e - emA), fpA = p2n(ne - emA);
        float aE = fmaf(mE, fsA, nO * fpA) * qb0[j];
        float aO = fmaf(mE + mO, fsA, nO * (skip ? fpA : 0.f)) * q11[j];
        float aX = last ? (mX + mO) * fsA * qb0[j] : 0.f;
        // recomputed neighbor state 2i-1 in frame emP
        int   emP = max(ne, n2e);
        float fsP = p2n(ne - emP), fpP = p2n(n2e - emP);
        float aP  = fmaf(nE + nO, fsP, n2O * (skipP ? fpP : 0.f)) * q1p[j];

        // ---- step B (t = 2k+1): frame emB ----
        int   emB = max(emA, emP);
        float fsB = p2n(emA - emB), fpB = p2n(emP - emB);
        float bE = fmaf(aE, fsB, aP * fpB) * qb1[j];
        float bO = fmaf(aE + aO, fsB, aP * (skip ? fpB : 0.f)) * q12[j];
        float bX = last ? (aX + aO) * fsB * qb1[j] : 0.f;

        // ---- renorm ----
        float big = fmaxf(bE, bO);
        if (last) big = fmaxf(big, bX);
        int ad = (__float_as_int(big) >> 23) - 127;
        e = emB + ad;
        float sc = p2n(-ad);
        mE = bE * sc; mO = bO * sc;
        if (last) mX = bX * sc;

        if (w < NWARP - 1) {
            if (lane == 31) { hE31[parW][w] = mE; hO31[parW][w] = mO; he31[parW][w] = e; }
            if (lane == 30) { hO30[parW][w] = mO; he30[parW][w] = e; }
        }

        // refill buffer j with pair k+3 (rows 2k+6, 2k+7)
        if (k + 3 <= 1023) {
            const float* rA = pb + (size_t)(2 * k + 6) * VV;
            const float* rB = rA + VV;
            qb0[j] = rA[0];   qb1[j] = rB[0];
            q11[j] = rA[ext]; q12[j] = rB[ext];
            q1p[j] = rA[extP];
        }
        __syncthreads();
    }

    // ----- readout -----
    sM[2 * tid]     = mE; sG[2 * tid]     = e;
    sM[2 * tid + 1] = mO; sG[2 * tid + 1] = e;
    if (last) { sM[2 * NTHR] = mX; sG[2 * NTHR] = e; }
    __syncthreads();
    if (tid == 0) {
        int il = 2 * sh_len, ip = il - 1;      // il in [256, 512]
        float ma = sM[il]; int ga = sG[il];
        float mb = sM[ip]; int gb = sG[ip];
        float la = (ma > 0.f) ? (float)ga + __log2f(ma) : -3.0e8f;
        float lb = (mb > 0.f) ? (float)gb + __log2f(mb) : -3.0e8f;
        float mx = fmaxf(la, lb);
        float ll2 = mx + __log2f(exp2f(la - mx) + exp2f(lb - mx));
        g_loss[b] = -ll2 * LN2F;
    }
}

// ---------------------------------------------------------------------------
// Pass 3: mean over batch + 1e-7
// ---------------------------------------------------------------------------
__global__ void finalize_kernel(float* __restrict__ out) {
    int t = threadIdx.x;
    float v = g_loss[t];
    #pragma unroll
    for (int o = 16; o > 0; o >>= 1)
        v += __shfl_xor_sync(0xffffffffu, v, o);
    if (t == 0) out[0] = v * (1.0f / (float)BB) + 1e-7f;
}

extern "C" void kernel_launch(void* const* d_in, const int* in_sizes, int n_in,
                              void* d_out, int out_size) {
    const float* y_pred = (const float*)d_in[0];
    const int*   y_true = (const int*)d_in[1];
    float*       out    = (float*)d_out;

    prob_kernel<<<(BB * TT) / 8, 256>>>(y_pred);
    ctc_kernel<<<BB, NTHR>>>(y_true);
    finalize_kernel<<<1, 32>>>(out);
}